// round 11
// baseline (speedup 1.0000x reference)
#include <cuda_runtime.h>

#define VOCAB  50000
#define EMBED  256
#define MAXLEN 512
#define UNITS  32
#define F1     16
#define BATCH  512

typedef unsigned long long ull;

// Scratch: P = emb_table @ Wx + b  [VOCAB, UNITS]  (6.4 MB, L2-resident)
__device__ float g_P[VOCAB * UNITS];

// ---- packed / MUFU helpers (sm_103a) --------------------------------------
__device__ __forceinline__ ull pack2(float lo, float hi) {
    ull d; asm("mov.b64 %0, {%1, %2};" : "=l"(d) : "f"(lo), "f"(hi)); return d;
}
__device__ __forceinline__ ull fma2(ull a, ull b, ull c) {
    ull d; asm("fma.rn.f32x2 %0, %1, %2, %3;" : "=l"(d) : "l"(a), "l"(b), "l"(c)); return d;
}
__device__ __forceinline__ ull add2(ull a, ull b) {
    ull d; asm("add.rn.f32x2 %0, %1, %2;" : "=l"(d) : "l"(a), "l"(b)); return d;
}
__device__ __forceinline__ void unpack2(ull s, float& lo, float& hi) {
    asm("mov.b64 {%0, %1}, %2;" : "=f"(lo), "=f"(hi) : "l"(s));
}
__device__ __forceinline__ float ex2f(float x) {
    float y; asm("ex2.approx.f32 %0, %1;" : "=f"(y) : "f"(x)); return y;
}
__device__ __forceinline__ float rcpf(float x) {
    float y; asm("rcp.approx.f32 %0, %1;" : "=f"(y) : "f"(x)); return y;
}
__device__ __forceinline__ float tanhf_mufu(float x) {
    float y; asm("tanh.approx.f32 %0, %1;" : "=f"(y) : "f"(x)); return y;
}

// ---------------------------------------------------------------------------
// Kernel 1: P[v][j] = sum_e emb[v][e]*Wx[e][j] + b[j]
// ROUND-9 VERSION VERBATIM (measured 16.7us — best).
// ---------------------------------------------------------------------------
#define PK_ROWS    64
#define PK_THREADS 128
#define WXT_STRIDE 258
#define PK_SMEM    ((UNITS*WXT_STRIDE + PK_ROWS*EMBED) * 4)   // ~33KB + 64KB

__global__ void __launch_bounds__(PK_THREADS, 1)
compute_P_kernel(const float* __restrict__ emb, const float* __restrict__ Wx,
                 const float* __restrict__ bias)
{
    extern __shared__ float smem[];
    float* wxT   = smem;                         // [UNITS][WXT_STRIDE]
    float* emb_s = smem + UNITS * WXT_STRIDE;    // [PK_ROWS][EMBED]

    const int tid = threadIdx.x;
    const int v0  = blockIdx.x * PK_ROWS;

    #pragma unroll
    for (int i = tid; i < EMBED * UNITS; i += PK_THREADS) {
        int j = i & 31, e = i >> 5;
        wxT[j * WXT_STRIDE + e] = Wx[i];
    }

    {
        const float4* e4  = reinterpret_cast<const float4*>(emb);
        float4*       es4 = reinterpret_cast<float4*>(emb_s);
        const int base4 = v0 * (EMBED / 4);
        const int max4  = VOCAB * (EMBED / 4);
        #pragma unroll
        for (int i = tid; i < PK_ROWS * (EMBED / 4); i += PK_THREADS) {
            int gi = base4 + i;
            es4[i] = (gi < max4) ? e4[gi] : make_float4(0.f, 0.f, 0.f, 0.f);
        }
    }
    __syncthreads();

    const int p  = tid & 15;
    const int rg = tid >> 4;

    const ull* wp = reinterpret_cast<const ull*>(wxT + p * WXT_STRIDE);
    const ull* wq = reinterpret_cast<const ull*>(wxT + (p + 16) * WXT_STRIDE);
    const float* er = emb_s + rg * 8 * EMBED;

    ull accP[8] = {0,0,0,0,0,0,0,0}, accQ[8] = {0,0,0,0,0,0,0,0};

    #pragma unroll 4
    for (int e = 0; e < EMBED; e += 4) {
        ull wp0 = wp[(e >> 1)];
        ull wp1 = wp[(e >> 1) + 1];
        ull wq0 = wq[(e >> 1)];
        ull wq1 = wq[(e >> 1) + 1];
        #pragma unroll
        for (int r = 0; r < 8; r++) {
            ulonglong2 ev = *reinterpret_cast<const ulonglong2*>(er + r * EMBED + e);
            accP[r] = fma2(ev.x, wp0, accP[r]);
            accP[r] = fma2(ev.y, wp1, accP[r]);
            accQ[r] = fma2(ev.x, wq0, accQ[r]);
            accQ[r] = fma2(ev.y, wq1, accQ[r]);
        }
    }

    const float bp = bias[p], bq = bias[p + 16];
    #pragma unroll
    for (int r = 0; r < 8; r++) {
        int v = v0 + rg * 8 + r;
        if (v < VOCAB) {
            float lo, hi;
            unpack2(accP[r], lo, hi);
            g_P[v * UNITS + p] = lo + hi + bp;
            unpack2(accQ[r], lo, hi);
            g_P[v * UNITS + p + 16] = lo + hi + bq;
        }
    }
}

// ---------------------------------------------------------------------------
// Kernel 2: RNN recurrence + head. TWO batch rows per warp, lane = unit.
// h packed per lane as f32x2 {hA, hB}; the packed SIMD dim is the ROW.
//   z{A,B}[lane] = P{A,B}[tok] + sum_k {hA_k,hB_k} * {w_k,lane, w_k,lane}
// Row B's instructions are independent of row A's chain -> in-order issue
// stalls get filled (round-10 analysis: wall = 512*max(chain, issue), and
// single-row bodies leave ~90cyc/step of stall unfilled).
// Exchange (1 STS.64 + syncwarp + 16 LDS.128), token LDS (int2 pair), and
// loop overhead are all SHARED between the two rows. Token pipelining and
// LDG-before-STS ordering kept from round 8.
// ---------------------------------------------------------------------------
#define R_WARPS   4
#define R_THREADS 128
#define TOKPAD    (MAXLEN + 8)

__global__ void __launch_bounds__(R_THREADS, 1)
rnn_kernel(const int*   __restrict__ tokens,
           const float* __restrict__ W1,
           const float* __restrict__ b1,
           const float* __restrict__ W2,
           const float* __restrict__ b2,
           const float* __restrict__ Wh,
           float*       __restrict__ out)
{
    __shared__ __align__(16) ull h_s[R_WARPS][2][UNITS];
    __shared__ __align__(16) int2 tokp_s[R_WARPS][TOKPAD];

    const unsigned FULL = 0xffffffffu;
    const int tid  = threadIdx.x;
    const int lane = tid & 31;
    const int wid  = tid >> 5;
    const int rA   = (blockIdx.x * R_WARPS + wid) * 2;   // rows rA, rA+1

    // stage this block's 8 token rows interleaved into int2 pairs:
    // tokp_s[w][t] = { tokens[row 2w][t], tokens[row 2w+1][t] }
    {
        const int* tbase = tokens + blockIdx.x * R_WARPS * 2 * MAXLEN;
        #pragma unroll
        for (int i = tid; i < R_WARPS * 2 * MAXLEN; i += R_THREADS) {
            int row = i >> 9;          // local row 0..7
            int t   = i & (MAXLEN - 1);
            reinterpret_cast<int*>(&tokp_s[row >> 1][t])[row & 1] = tbase[i];
        }
        if (tid < R_WARPS * 8)
            tokp_s[tid >> 3][MAXLEN + (tid & 7)] = make_int2(0, 0);
    }
    __syncthreads();

    // duplicated packed weights: whd[k] = {Wh[k][lane], Wh[k][lane]}
    ull whd[UNITS];
    #pragma unroll
    for (int k = 0; k < UNITS; k++) {
        float w = Wh[k * UNITS + lane];
        whd[k] = pack2(w, w);
    }

    const int2* trow = tokp_s[wid];

    // prefetch ring of packed P rows {A,B} for steps t..t+2, token pair t+3
    int2 t0 = trow[0], t1 = trow[1], t2 = trow[2];
    ull pv0 = pack2(g_P[t0.x * UNITS + lane], g_P[t0.y * UNITS + lane]);
    ull pv1 = pack2(g_P[t1.x * UNITS + lane], g_P[t1.y * UNITS + lane]);
    ull pv2 = pack2(g_P[t2.x * UNITS + lane], g_P[t2.y * UNITS + lane]);
    int2 tokn = trow[3];

    float hA = 0.f, hB = 0.f;

    #pragma unroll 4
    for (int t = 0; t < MAXLEN; t++) {
        // LDGs use register tokens (loaded last iteration) -> no LDS stall
        float pA3 = g_P[tokn.x * UNITS + lane];
        float pB3 = g_P[tokn.y * UNITS + lane];
        int2 toknext = trow[t + 4];

        // shared exchange: 1 STS.64 + 1 syncwarp for both rows
        ull* buf = h_s[wid][t & 1];
        buf[lane] = pack2(hA, hB);
        __syncwarp();
        const ulonglong2* hb = reinterpret_cast<const ulonglong2*>(buf);
        ulonglong2 u0 = hb[0],  u1 = hb[1],  u2 = hb[2],  u3 = hb[3];
        ulonglong2 u4 = hb[4],  u5 = hb[5],  u6 = hb[6],  u7 = hb[7];
        ulonglong2 u8 = hb[8],  u9 = hb[9],  u10 = hb[10], u11 = hb[11];
        ulonglong2 u12 = hb[12], u13 = hb[13], u14 = hb[14], u15 = hb[15];

        // 8 packed chains of depth 4 (32 fma2 = both rows' matvecs)
        ull A0 = fma2(u0.x, whd[0], pv0);
        ull A1 = fma2(u0.y, whd[1], 0ULL);
        ull A2 = fma2(u1.x, whd[2], 0ULL);
        ull A3 = fma2(u1.y, whd[3], 0ULL);
        ull A4 = fma2(u2.x, whd[4], 0ULL);
        ull A5 = fma2(u2.y, whd[5], 0ULL);
        ull A6 = fma2(u3.x, whd[6], 0ULL);
        ull A7 = fma2(u3.y, whd[7], 0ULL);
        A0 = fma2(u4.x,  whd[8],  A0);
        A1 = fma2(u4.y,  whd[9],  A1);
        A2 = fma2(u5.x,  whd[10], A2);
        A3 = fma2(u5.y,  whd[11], A3);
        A4 = fma2(u6.x,  whd[12], A4);
        A5 = fma2(u6.y,  whd[13], A5);
        A6 = fma2(u7.x,  whd[14], A6);
        A7 = fma2(u7.y,  whd[15], A7);
        A0 = fma2(u8.x,  whd[16], A0);
        A1 = fma2(u8.y,  whd[17], A1);
        A2 = fma2(u9.x,  whd[18], A2);
        A3 = fma2(u9.y,  whd[19], A3);
        A4 = fma2(u10.x, whd[20], A4);
        A5 = fma2(u10.y, whd[21], A5);
        A6 = fma2(u11.x, whd[22], A6);
        A7 = fma2(u11.y, whd[23], A7);
        A0 = fma2(u12.x, whd[24], A0);
        A1 = fma2(u12.y, whd[25], A1);
        A2 = fma2(u13.x, whd[26], A2);
        A3 = fma2(u13.y, whd[27], A3);
        A4 = fma2(u14.x, whd[28], A4);
        A5 = fma2(u14.y, whd[29], A5);
        A6 = fma2(u15.x, whd[30], A6);
        A7 = fma2(u15.y, whd[31], A7);

        ull B0 = add2(A0, A1), B1 = add2(A2, A3);
        ull B2 = add2(A4, A5), B3 = add2(A6, A7);
        ull D  = add2(add2(B0, B1), add2(B2, B3));
        float zA, zB; unpack2(D, zA, zB);

        hA = tanhf_mufu(zA);
        hB = tanhf_mufu(zB);

        pv0 = pv1; pv1 = pv2; pv2 = pack2(pA3, pB3); tokn = toknext;
    }

    // ---- head (per row): z = (h @ W1 + b1) @ W2 + b2 ; out = sigmoid(z) ----
    float w1c[UNITS];
    #pragma unroll
    for (int k = 0; k < UNITS; k++)
        w1c[k] = (lane < F1) ? W1[k * F1 + lane] : 0.f;
    const float b1v = (lane < F1) ? b1[lane] : 0.f;
    const float w2v = (lane < F1) ? W2[lane] : 0.f;
    const float b2v = b2[0];

    float hh0 = hA, hh1 = hB;
    #pragma unroll
    for (int rr = 0; rr < 2; rr++) {
        float h = (rr == 0) ? hh0 : hh1;
        float y = b1v;
        #pragma unroll
        for (int k = 0; k < UNITS; k++)
            y = fmaf(__shfl_sync(FULL, h, k), w1c[k], y);
        float contrib = y * w2v;
        #pragma unroll
        for (int off = 16; off > 0; off >>= 1)
            contrib += __shfl_xor_sync(FULL, contrib, off);
        if (lane == 0) {
            float zz = contrib + b2v;
            out[rA + rr] = rcpf(1.f + ex2f(-1.4426950408889634f * zz));
        }
    }
}

// ---------------------------------------------------------------------------
extern "C" void kernel_launch(void* const* d_in, const int* in_sizes, int n_in,
                              void* d_out, int out_size)
{
    const int*   tokens = (const int*)  d_in[0];
    const float* emb    = (const float*)d_in[1];
    const float* Wx     = (const float*)d_in[2];
    const float* Wh     = (const float*)d_in[3];
    const float* bias   = (const float*)d_in[4];
    const float* W1     = (const float*)d_in[5];
    const float* b1     = (const float*)d_in[6];
    const float* W2     = (const float*)d_in[7];
    const float* b2     = (const float*)d_in[8];
    float* out = (float*)d_out;

    cudaFuncSetAttribute((const void*)compute_P_kernel,
                         cudaFuncAttributeMaxDynamicSharedMemorySize, PK_SMEM);

    compute_P_kernel<<<(VOCAB + PK_ROWS - 1) / PK_ROWS, PK_THREADS, PK_SMEM>>>(emb, Wx, bias);
    rnn_kernel<<<BATCH / (R_WARPS * 2), R_THREADS>>>(tokens, W1, b1, W2, b2, Wh, out);
}

// round 12
// speedup vs baseline: 1.0893x; 1.0893x over previous
#include <cuda_runtime.h>

#define VOCAB  50000
#define EMBED  256
#define MAXLEN 512
#define UNITS  32
#define F1     16
#define BATCH  512

typedef unsigned long long ull;

// Scratch: P = emb_table @ Wx + b  [VOCAB, UNITS]  (6.4 MB, L2-resident)
__device__ float g_P[VOCAB * UNITS];

// ---- packed / MUFU helpers (sm_103a) --------------------------------------
__device__ __forceinline__ ull pack2(float lo, float hi) {
    ull d; asm("mov.b64 %0, {%1, %2};" : "=l"(d) : "f"(lo), "f"(hi)); return d;
}
__device__ __forceinline__ ull fma2(ull a, ull b, ull c) {
    ull d; asm("fma.rn.f32x2 %0, %1, %2, %3;" : "=l"(d) : "l"(a), "l"(b), "l"(c)); return d;
}
__device__ __forceinline__ ull add2(ull a, ull b) {
    ull d; asm("add.rn.f32x2 %0, %1, %2;" : "=l"(d) : "l"(a), "l"(b)); return d;
}
__device__ __forceinline__ void unpack2(ull s, float& lo, float& hi) {
    asm("mov.b64 {%0, %1}, %2;" : "=f"(lo), "=f"(hi) : "l"(s));
}
__device__ __forceinline__ float ex2f(float x) {
    float y; asm("ex2.approx.f32 %0, %1;" : "=f"(y) : "f"(x)); return y;
}
__device__ __forceinline__ float rcpf(float x) {
    float y; asm("rcp.approx.f32 %0, %1;" : "=f"(y) : "f"(x)); return y;
}
__device__ __forceinline__ float tanhf_mufu(float x) {
    float y; asm("tanh.approx.f32 %0, %1;" : "=f"(y) : "f"(x)); return y;
}

// ---------------------------------------------------------------------------
// Kernel 1: P[v][j] = sum_e emb[v][e]*Wx[e][j] + b[j]
// ROUND-9 VERSION VERBATIM (measured 16.7us — best).
// ---------------------------------------------------------------------------
#define PK_ROWS    64
#define PK_THREADS 128
#define WXT_STRIDE 258
#define PK_SMEM    ((UNITS*WXT_STRIDE + PK_ROWS*EMBED) * 4)   // ~33KB + 64KB

__global__ void __launch_bounds__(PK_THREADS, 1)
compute_P_kernel(const float* __restrict__ emb, const float* __restrict__ Wx,
                 const float* __restrict__ bias)
{
    extern __shared__ float smem[];
    float* wxT   = smem;                         // [UNITS][WXT_STRIDE]
    float* emb_s = smem + UNITS * WXT_STRIDE;    // [PK_ROWS][EMBED]

    const int tid = threadIdx.x;
    const int v0  = blockIdx.x * PK_ROWS;

    #pragma unroll
    for (int i = tid; i < EMBED * UNITS; i += PK_THREADS) {
        int j = i & 31, e = i >> 5;
        wxT[j * WXT_STRIDE + e] = Wx[i];
    }

    {
        const float4* e4  = reinterpret_cast<const float4*>(emb);
        float4*       es4 = reinterpret_cast<float4*>(emb_s);
        const int base4 = v0 * (EMBED / 4);
        const int max4  = VOCAB * (EMBED / 4);
        #pragma unroll
        for (int i = tid; i < PK_ROWS * (EMBED / 4); i += PK_THREADS) {
            int gi = base4 + i;
            es4[i] = (gi < max4) ? e4[gi] : make_float4(0.f, 0.f, 0.f, 0.f);
        }
    }
    __syncthreads();

    const int p  = tid & 15;
    const int rg = tid >> 4;

    const ull* wp = reinterpret_cast<const ull*>(wxT + p * WXT_STRIDE);
    const ull* wq = reinterpret_cast<const ull*>(wxT + (p + 16) * WXT_STRIDE);
    const float* er = emb_s + rg * 8 * EMBED;

    ull accP[8] = {0,0,0,0,0,0,0,0}, accQ[8] = {0,0,0,0,0,0,0,0};

    #pragma unroll 4
    for (int e = 0; e < EMBED; e += 4) {
        ull wp0 = wp[(e >> 1)];
        ull wp1 = wp[(e >> 1) + 1];
        ull wq0 = wq[(e >> 1)];
        ull wq1 = wq[(e >> 1) + 1];
        #pragma unroll
        for (int r = 0; r < 8; r++) {
            ulonglong2 ev = *reinterpret_cast<const ulonglong2*>(er + r * EMBED + e);
            accP[r] = fma2(ev.x, wp0, accP[r]);
            accP[r] = fma2(ev.y, wp1, accP[r]);
            accQ[r] = fma2(ev.x, wq0, accQ[r]);
            accQ[r] = fma2(ev.y, wq1, accQ[r]);
        }
    }

    const float bp = bias[p], bq = bias[p + 16];
    #pragma unroll
    for (int r = 0; r < 8; r++) {
        int v = v0 + rg * 8 + r;
        if (v < VOCAB) {
            float lo, hi;
            unpack2(accP[r], lo, hi);
            g_P[v * UNITS + p] = lo + hi + bp;
            unpack2(accQ[r], lo, hi);
            g_P[v * UNITS + p + 16] = lo + hi + bq;
        }
    }
}

// ---------------------------------------------------------------------------
// Kernel 2: RNN recurrence + head. ROUND-10/8 BODY VERBATIM (one row per
// warp, lane = unit; best measured per-warp config). SINGLE CHANGE:
// launched as 64 blocks x 8 warps -> 2 warps per SMSP. Round-11 proved
// single-row bodies leave large unfilled stall windows (issue-sum ~73cyc
// vs step ~232cyc); a co-resident warp fills them with ZERO added
// instructions per warp. (Round-2's 1-warp/SMSP choice was tuned for the
// old MIO-heavy 34-SHFL body; the lean body changes the arithmetic.)
// ---------------------------------------------------------------------------
#define R_WARPS   8
#define R_THREADS 256
#define TOKPAD    (MAXLEN + 8)

__global__ void __launch_bounds__(R_THREADS, 1)
rnn_kernel(const int*   __restrict__ tokens,
           const float* __restrict__ W1,
           const float* __restrict__ b1,
           const float* __restrict__ W2,
           const float* __restrict__ b2,
           const float* __restrict__ Wh,
           float*       __restrict__ out)
{
    __shared__ __align__(16) float h_s[R_WARPS][2][UNITS];
    __shared__ __align__(16) int tok_s[R_WARPS][TOKPAD];

    const unsigned FULL = 0xffffffffu;
    const int tid  = threadIdx.x;
    const int lane = tid & 31;
    const int wid  = tid >> 5;
    const int b    = blockIdx.x * R_WARPS + wid;

    // stage this block's 8 token rows (int4), pad 8 entries per row with 0
    {
        const int4* src = reinterpret_cast<const int4*>(tokens + blockIdx.x * R_WARPS * MAXLEN);
        #pragma unroll
        for (int i = tid; i < R_WARPS * (MAXLEN / 4); i += R_THREADS) {
            int row = i >> 7;              // MAXLEN/4 = 128 int4 per row
            int col = i & 127;
            reinterpret_cast<int4*>(&tok_s[row][0])[col] = src[i];
        }
        if (tid < R_WARPS * 8)
            tok_s[tid >> 3][MAXLEN + (tid & 7)] = 0;
    }
    __syncthreads();

    // packed weights: whp[p] = {Wh[2p][lane], Wh[2p+1][lane]}
    ull whp[UNITS / 2];
    #pragma unroll
    for (int p = 0; p < UNITS / 2; p++)
        whp[p] = pack2(Wh[(2 * p) * UNITS + lane], Wh[(2 * p + 1) * UNITS + lane]);

    const int* trow = tok_s[wid];

    // prefetch ring: P rows for steps t, t+1, t+2 plus the TOKEN for t+3
    float pv0 = g_P[trow[0] * UNITS + lane];
    float pv1 = g_P[trow[1] * UNITS + lane];
    float pv2 = g_P[trow[2] * UNITS + lane];
    int   tokn = trow[3];

    float h = 0.f;

    #pragma unroll 4
    for (int t = 0; t < MAXLEN; t++) {
        // LDG uses a register token (loaded last iteration) -> no LDS stall
        float pv3 = g_P[tokn * UNITS + lane];
        // token for step t+4, consumed NEXT iteration (padded: no bounds SEL)
        int toknext = trow[t + 4];

        // exchange h across the warp (double-buffered, one syncwarp)
        float* buf = h_s[wid][t & 1];
        buf[lane] = h;
        __syncwarp();
        const ulonglong2* hb = reinterpret_cast<const ulonglong2*>(buf);
        ulonglong2 v0 = hb[0], v1 = hb[1], v2 = hb[2], v3 = hb[3];
        ulonglong2 v4 = hb[4], v5 = hb[5], v6 = hb[6], v7 = hb[7];

        // 8 chains of depth 2
        ull A0 = fma2(v0.x, whp[0],  pack2(pv0, 0.f));
        ull A1 = fma2(v0.y, whp[1],  0ULL);
        ull A2 = fma2(v1.x, whp[2],  0ULL);
        ull A3 = fma2(v1.y, whp[3],  0ULL);
        ull A4 = fma2(v2.x, whp[4],  0ULL);
        ull A5 = fma2(v2.y, whp[5],  0ULL);
        ull A6 = fma2(v3.x, whp[6],  0ULL);
        ull A7 = fma2(v3.y, whp[7],  0ULL);
        A0 = fma2(v4.x, whp[8],  A0);
        A1 = fma2(v4.y, whp[9],  A1);
        A2 = fma2(v5.x, whp[10], A2);
        A3 = fma2(v5.y, whp[11], A3);
        A4 = fma2(v6.x, whp[12], A4);
        A5 = fma2(v6.y, whp[13], A5);
        A6 = fma2(v7.x, whp[14], A6);
        A7 = fma2(v7.y, whp[15], A7);

        ull B0 = add2(A0, A1), B1 = add2(A2, A3);
        ull B2 = add2(A4, A5), B3 = add2(A6, A7);
        ull D  = add2(add2(B0, B1), add2(B2, B3));
        float zlo, zhi; unpack2(D, zlo, zhi);

        h = tanhf_mufu(zlo + zhi);

        pv0 = pv1; pv1 = pv2; pv2 = pv3; tokn = toknext;
    }

    // ---- head: z = (h @ W1 + b1) @ W2 + b2 ; out = sigmoid(z) ----
    float w1c[UNITS];
    #pragma unroll
    for (int k = 0; k < UNITS; k++)
        w1c[k] = (lane < F1) ? W1[k * F1 + lane] : 0.f;

    float y = (lane < F1) ? b1[lane] : 0.f;
    #pragma unroll
    for (int k = 0; k < UNITS; k++)
        y = fmaf(__shfl_sync(FULL, h, k), w1c[k], y);

    float w2v = (lane < F1) ? W2[lane] : 0.f;
    float contrib = y * w2v;
    #pragma unroll
    for (int off = 16; off > 0; off >>= 1)
        contrib += __shfl_xor_sync(FULL, contrib, off);

    if (lane == 0) {
        float zz = contrib + b2[0];
        out[b] = rcpf(1.f + ex2f(-1.4426950408889634f * zz));
    }
}

// ---------------------------------------------------------------------------
extern "C" void kernel_launch(void* const* d_in, const int* in_sizes, int n_in,
                              void* d_out, int out_size)
{
    const int*   tokens = (const int*)  d_in[0];
    const float* emb    = (const float*)d_in[1];
    const float* Wx     = (const float*)d_in[2];
    const float* Wh     = (const float*)d_in[3];
    const float* bias   = (const float*)d_in[4];
    const float* W1     = (const float*)d_in[5];
    const float* b1     = (const float*)d_in[6];
    const float* W2     = (const float*)d_in[7];
    const float* b2     = (const float*)d_in[8];
    float* out = (float*)d_out;

    cudaFuncSetAttribute((const void*)compute_P_kernel,
                         cudaFuncAttributeMaxDynamicSharedMemorySize, PK_SMEM);

    compute_P_kernel<<<(VOCAB + PK_ROWS - 1) / PK_ROWS, PK_THREADS, PK_SMEM>>>(emb, Wx, bias);
    rnn_kernel<<<BATCH / R_WARPS, R_THREADS>>>(tokens, W1, b1, W2, b2, Wh, out);
}

// round 13
// speedup vs baseline: 1.1416x; 1.0480x over previous
#include <cuda_runtime.h>

#define VOCAB  50000
#define EMBED  256
#define MAXLEN 512
#define UNITS  32
#define F1     16
#define BATCH  512

typedef unsigned long long ull;

// Scratch: P = emb_table @ Wx + b  [VOCAB, UNITS]  (6.4 MB, L2-resident)
__device__ float g_P[VOCAB * UNITS];

// ---- packed / MUFU helpers (sm_103a) --------------------------------------
__device__ __forceinline__ ull pack2(float lo, float hi) {
    ull d; asm("mov.b64 %0, {%1, %2};" : "=l"(d) : "f"(lo), "f"(hi)); return d;
}
__device__ __forceinline__ ull fma2(ull a, ull b, ull c) {
    ull d; asm("fma.rn.f32x2 %0, %1, %2, %3;" : "=l"(d) : "l"(a), "l"(b), "l"(c)); return d;
}
__device__ __forceinline__ ull add2(ull a, ull b) {
    ull d; asm("add.rn.f32x2 %0, %1, %2;" : "=l"(d) : "l"(a), "l"(b)); return d;
}
__device__ __forceinline__ void unpack2(ull s, float& lo, float& hi) {
    asm("mov.b64 {%0, %1}, %2;" : "=f"(lo), "=f"(hi) : "l"(s));
}
__device__ __forceinline__ float ex2f(float x) {
    float y; asm("ex2.approx.f32 %0, %1;" : "=f"(y) : "f"(x)); return y;
}
__device__ __forceinline__ float rcpf(float x) {
    float y; asm("rcp.approx.f32 %0, %1;" : "=f"(y) : "f"(x)); return y;
}
__device__ __forceinline__ float tanhf_mufu(float x) {
    float y; asm("tanh.approx.f32 %0, %1;" : "=f"(y) : "f"(x)); return y;
}

// ---------------------------------------------------------------------------
// Kernel 1: P[v][j] = sum_e emb[v][e]*Wx[e][j] + b[j]
// CHANGE vs round 9: tile halved to 32 rows (emb 32KB + wxT 33KB = 65KB
// smem) so 2-3 blocks co-reside per SM -> block n+1's DRAM staging
// overlaps block n's compute (round-9's 97KB + minBlocks=1 serialized the
// 64KB emb load ahead of compute every wave; 16.7us vs 11.4 fma2 roofline).
// Math layout per thread unchanged: 2 cols (p, p+16) x 4 rows, K-pair
// packed partials, LDS.64 weight loads (rows 8B-aligned).
// ---------------------------------------------------------------------------
#define PK_ROWS    32
#define PK_THREADS 128
#define WXT_STRIDE 258
#define PK_SMEM    ((UNITS*WXT_STRIDE + PK_ROWS*EMBED) * 4)   // ~33KB + 32KB

__global__ void __launch_bounds__(PK_THREADS)
compute_P_kernel(const float* __restrict__ emb, const float* __restrict__ Wx,
                 const float* __restrict__ bias)
{
    extern __shared__ float smem[];
    float* wxT   = smem;                         // [UNITS][WXT_STRIDE]
    float* emb_s = smem + UNITS * WXT_STRIDE;    // [PK_ROWS][EMBED]

    const int tid = threadIdx.x;
    const int v0  = blockIdx.x * PK_ROWS;

    #pragma unroll
    for (int i = tid; i < EMBED * UNITS; i += PK_THREADS) {
        int j = i & 31, e = i >> 5;
        wxT[j * WXT_STRIDE + e] = Wx[i];
    }

    {
        const float4* e4  = reinterpret_cast<const float4*>(emb);
        float4*       es4 = reinterpret_cast<float4*>(emb_s);
        const int base4 = v0 * (EMBED / 4);
        const int max4  = VOCAB * (EMBED / 4);
        #pragma unroll
        for (int i = tid; i < PK_ROWS * (EMBED / 4); i += PK_THREADS) {
            int gi = base4 + i;
            es4[i] = (gi < max4) ? e4[gi] : make_float4(0.f, 0.f, 0.f, 0.f);
        }
    }
    __syncthreads();

    const int p  = tid & 15;          // columns p and p+16
    const int rg = tid >> 4;          // rows rg*4 .. rg*4+3 (8 groups x 4)

    const ull* wp = reinterpret_cast<const ull*>(wxT + p * WXT_STRIDE);
    const ull* wq = reinterpret_cast<const ull*>(wxT + (p + 16) * WXT_STRIDE);
    const float* er = emb_s + rg * 4 * EMBED;

    ull accP[4] = {0,0,0,0}, accQ[4] = {0,0,0,0};

    #pragma unroll 8
    for (int e = 0; e < EMBED; e += 4) {
        ull wp0 = wp[(e >> 1)];
        ull wp1 = wp[(e >> 1) + 1];
        ull wq0 = wq[(e >> 1)];
        ull wq1 = wq[(e >> 1) + 1];
        #pragma unroll
        for (int r = 0; r < 4; r++) {
            ulonglong2 ev = *reinterpret_cast<const ulonglong2*>(er + r * EMBED + e);
            accP[r] = fma2(ev.x, wp0, accP[r]);
            accP[r] = fma2(ev.y, wp1, accP[r]);
            accQ[r] = fma2(ev.x, wq0, accQ[r]);
            accQ[r] = fma2(ev.y, wq1, accQ[r]);
        }
    }

    const float bp = bias[p], bq = bias[p + 16];
    #pragma unroll
    for (int r = 0; r < 4; r++) {
        int v = v0 + rg * 4 + r;
        if (v < VOCAB) {
            float lo, hi;
            unpack2(accP[r], lo, hi);
            g_P[v * UNITS + p] = lo + hi + bp;
            unpack2(accQ[r], lo, hi);
            g_P[v * UNITS + p + 16] = lo + hi + bq;
        }
    }
}

// ---------------------------------------------------------------------------
// Kernel 2: RNN recurrence + head. ROUND-10 VERSION VERBATIM (measured
// 63.2us — best; round 12 proved wall = 512 x single-warp chain, layout
// 128 blocks x 4 warps = 1 warp/SMSP on 128 SMs is optimal for 512 rows).
// ---------------------------------------------------------------------------
#define R_WARPS   4
#define R_THREADS 128
#define TOKPAD    (MAXLEN + 8)

__global__ void __launch_bounds__(R_THREADS, 1)
rnn_kernel(const int*   __restrict__ tokens,
           const float* __restrict__ W1,
           const float* __restrict__ b1,
           const float* __restrict__ W2,
           const float* __restrict__ b2,
           const float* __restrict__ Wh,
           float*       __restrict__ out)
{
    __shared__ __align__(16) float h_s[R_WARPS][2][UNITS];
    __shared__ __align__(16) int tok_s[R_WARPS][TOKPAD];

    const unsigned FULL = 0xffffffffu;
    const int tid  = threadIdx.x;
    const int lane = tid & 31;
    const int wid  = tid >> 5;
    const int b    = blockIdx.x * R_WARPS + wid;

    // stage this block's 4 token rows (int4), pad 8 entries per row with 0
    {
        const int4* src = reinterpret_cast<const int4*>(tokens + blockIdx.x * R_WARPS * MAXLEN);
        #pragma unroll
        for (int i = tid; i < R_WARPS * (MAXLEN / 4); i += R_THREADS) {
            int row = i >> 7;
            int col = i & 127;
            reinterpret_cast<int4*>(&tok_s[row][0])[col] = src[i];
        }
        if (tid < R_WARPS * 8)
            tok_s[tid >> 3][MAXLEN + (tid & 7)] = 0;
    }
    __syncthreads();

    // packed weights: whp[p] = {Wh[2p][lane], Wh[2p+1][lane]}
    ull whp[UNITS / 2];
    #pragma unroll
    for (int p = 0; p < UNITS / 2; p++)
        whp[p] = pack2(Wh[(2 * p) * UNITS + lane], Wh[(2 * p + 1) * UNITS + lane]);

    const int* trow = tok_s[wid];

    // prefetch ring: P rows for steps t, t+1, t+2 plus the TOKEN for t+3
    float pv0 = g_P[trow[0] * UNITS + lane];
    float pv1 = g_P[trow[1] * UNITS + lane];
    float pv2 = g_P[trow[2] * UNITS + lane];
    int   tokn = trow[3];

    float h = 0.f;

    #pragma unroll 4
    for (int t = 0; t < MAXLEN; t++) {
        // LDG uses a register token (loaded last iteration) -> no LDS stall
        float pv3 = g_P[tokn * UNITS + lane];
        // token for step t+4, consumed NEXT iteration (padded: no bounds SEL)
        int toknext = trow[t + 4];

        // exchange h across the warp (double-buffered, one syncwarp)
        float* buf = h_s[wid][t & 1];
        buf[lane] = h;
        __syncwarp();
        const ulonglong2* hb = reinterpret_cast<const ulonglong2*>(buf);
        ulonglong2 v0 = hb[0], v1 = hb[1], v2 = hb[2], v3 = hb[3];
        ulonglong2 v4 = hb[4], v5 = hb[5], v6 = hb[6], v7 = hb[7];

        // 8 chains of depth 2
        ull A0 = fma2(v0.x, whp[0],  pack2(pv0, 0.f));
        ull A1 = fma2(v0.y, whp[1],  0ULL);
        ull A2 = fma2(v1.x, whp[2],  0ULL);
        ull A3 = fma2(v1.y, whp[3],  0ULL);
        ull A4 = fma2(v2.x, whp[4],  0ULL);
        ull A5 = fma2(v2.y, whp[5],  0ULL);
        ull A6 = fma2(v3.x, whp[6],  0ULL);
        ull A7 = fma2(v3.y, whp[7],  0ULL);
        A0 = fma2(v4.x, whp[8],  A0);
        A1 = fma2(v4.y, whp[9],  A1);
        A2 = fma2(v5.x, whp[10], A2);
        A3 = fma2(v5.y, whp[11], A3);
        A4 = fma2(v6.x, whp[12], A4);
        A5 = fma2(v6.y, whp[13], A5);
        A6 = fma2(v7.x, whp[14], A6);
        A7 = fma2(v7.y, whp[15], A7);

        ull B0 = add2(A0, A1), B1 = add2(A2, A3);
        ull B2 = add2(A4, A5), B3 = add2(A6, A7);
        ull D  = add2(add2(B0, B1), add2(B2, B3));
        float zlo, zhi; unpack2(D, zlo, zhi);

        h = tanhf_mufu(zlo + zhi);

        pv0 = pv1; pv1 = pv2; pv2 = pv3; tokn = toknext;
    }

    // ---- head: z = (h @ W1 + b1) @ W2 + b2 ; out = sigmoid(z) ----
    float w1c[UNITS];
    #pragma unroll
    for (int k = 0; k < UNITS; k++)
        w1c[k] = (lane < F1) ? W1[k * F1 + lane] : 0.f;

    float y = (lane < F1) ? b1[lane] : 0.f;
    #pragma unroll
    for (int k = 0; k < UNITS; k++)
        y = fmaf(__shfl_sync(FULL, h, k), w1c[k], y);

    float w2v = (lane < F1) ? W2[lane] : 0.f;
    float contrib = y * w2v;
    #pragma unroll
    for (int off = 16; off > 0; off >>= 1)
        contrib += __shfl_xor_sync(FULL, contrib, off);

    if (lane == 0) {
        float zz = contrib + b2[0];
        out[b] = rcpf(1.f + ex2f(-1.4426950408889634f * zz));
    }
}

// ---------------------------------------------------------------------------
extern "C" void kernel_launch(void* const* d_in, const int* in_sizes, int n_in,
                              void* d_out, int out_size)
{
    const int*   tokens = (const int*)  d_in[0];
    const float* emb    = (const float*)d_in[1];
    const float* Wx     = (const float*)d_in[2];
    const float* Wh     = (const float*)d_in[3];
    const float* bias   = (const float*)d_in[4];
    const float* W1     = (const float*)d_in[5];
    const float* b1     = (const float*)d_in[6];
    const float* W2     = (const float*)d_in[7];
    const float* b2     = (const float*)d_in[8];
    float* out = (float*)d_out;

    cudaFuncSetAttribute((const void*)compute_P_kernel,
                         cudaFuncAttributeMaxDynamicSharedMemorySize, PK_SMEM);

    compute_P_kernel<<<(VOCAB + PK_ROWS - 1) / PK_ROWS, PK_THREADS, PK_SMEM>>>(emb, Wx, bias);
    rnn_kernel<<<BATCH / R_WARPS, R_THREADS>>>(tokens, W1, b1, W2, b2, Wh, out);
}

// round 14
// speedup vs baseline: 1.1420x; 1.0004x over previous
#include <cuda_runtime.h>

#define VOCAB  50000
#define EMBED  256
#define MAXLEN 512
#define UNITS  32
#define F1     16
#define BATCH  512

typedef unsigned long long ull;

// Scratch: P = emb_table @ Wx + b  [VOCAB, UNITS]  (6.4 MB, L2-resident)
__device__ float g_P[VOCAB * UNITS];

// ---- packed / MUFU helpers (sm_103a) --------------------------------------
__device__ __forceinline__ ull pack2(float lo, float hi) {
    ull d; asm("mov.b64 %0, {%1, %2};" : "=l"(d) : "f"(lo), "f"(hi)); return d;
}
__device__ __forceinline__ ull fma2(ull a, ull b, ull c) {
    ull d; asm("fma.rn.f32x2 %0, %1, %2, %3;" : "=l"(d) : "l"(a), "l"(b), "l"(c)); return d;
}
__device__ __forceinline__ ull add2(ull a, ull b) {
    ull d; asm("add.rn.f32x2 %0, %1, %2;" : "=l"(d) : "l"(a), "l"(b)); return d;
}
__device__ __forceinline__ void unpack2(ull s, float& lo, float& hi) {
    asm("mov.b64 {%0, %1}, %2;" : "=f"(lo), "=f"(hi) : "l"(s));
}
__device__ __forceinline__ float ex2f(float x) {
    float y; asm("ex2.approx.f32 %0, %1;" : "=f"(y) : "f"(x)); return y;
}
__device__ __forceinline__ float rcpf(float x) {
    float y; asm("rcp.approx.f32 %0, %1;" : "=f"(y) : "f"(x)); return y;
}
__device__ __forceinline__ float tanhf_mufu(float x) {
    float y; asm("tanh.approx.f32 %0, %1;" : "=f"(y) : "f"(x)); return y;
}

// ---------------------------------------------------------------------------
// Kernel 1: P[v][j] = sum_e emb[v][e]*Wx[e][j] + b[j]
// CHANGE vs round 9: emb is read DIRECTLY from GMEM inside the fma2 loop —
// the smem tile gave zero reuse (each element consumed once; the 16 threads
// sharing a row read the same address -> LDG broadcast-coalesces to one
// request anyway). Kills the serial stage->sync->compute structure that
// kept round-9 at 16.7us vs the ~11us fma2 roofline. Only wxT (33KB) stays
// in smem -> many blocks/SM; 8 independent row streams per thread hide
// DRAM latency. 256 thr/block: p = tid&15 (2 cols), rg = tid>>4 (8 rows).
// ---------------------------------------------------------------------------
#define PK_THREADS    256
#define PK_BLOCK_ROWS 128
#define WXT_STRIDE    258
#define PK_SMEM       (UNITS * WXT_STRIDE * 4)   // ~33KB

__global__ void __launch_bounds__(PK_THREADS)
compute_P_kernel(const float* __restrict__ emb, const float* __restrict__ Wx,
                 const float* __restrict__ bias)
{
    extern __shared__ float wxT[];               // [UNITS][WXT_STRIDE]

    const int tid = threadIdx.x;

    // stage Wx transposed: wxT[j][e] = Wx[e][j]  (only smem use)
    #pragma unroll
    for (int i = tid; i < EMBED * UNITS; i += PK_THREADS) {
        int j = i & 31, e = i >> 5;
        wxT[j * WXT_STRIDE + e] = Wx[i];
    }
    __syncthreads();

    const int p  = tid & 15;                     // columns p and p+16
    const int rg = tid >> 4;                     // row group 0..15
    const int v0 = blockIdx.x * PK_BLOCK_ROWS + rg * 8;

    const ull* wp = reinterpret_cast<const ull*>(wxT + p * WXT_STRIDE);
    const ull* wq = reinterpret_cast<const ull*>(wxT + (p + 16) * WXT_STRIDE);

    // 8 row pointers into GMEM (rows clamped so OOB rows read row VOCAB-1)
    const ulonglong2* er[8];
    #pragma unroll
    for (int r = 0; r < 8; r++) {
        int v = v0 + r;
        int vc = (v < VOCAB) ? v : (VOCAB - 1);
        er[r] = reinterpret_cast<const ulonglong2*>(emb + (size_t)vc * EMBED);
    }

    ull accP[8] = {0,0,0,0,0,0,0,0}, accQ[8] = {0,0,0,0,0,0,0,0};

    #pragma unroll 4
    for (int e = 0; e < EMBED; e += 4) {
        ull wp0 = wp[(e >> 1)];
        ull wp1 = wp[(e >> 1) + 1];
        ull wq0 = wq[(e >> 1)];
        ull wq1 = wq[(e >> 1) + 1];
        #pragma unroll
        for (int r = 0; r < 8; r++) {
            ulonglong2 ev = er[r][e >> 2];        // LDG.128, broadcast x16
            accP[r] = fma2(ev.x, wp0, accP[r]);
            accP[r] = fma2(ev.y, wp1, accP[r]);
            accQ[r] = fma2(ev.x, wq0, accQ[r]);
            accQ[r] = fma2(ev.y, wq1, accQ[r]);
        }
    }

    const float bp = bias[p], bq = bias[p + 16];
    #pragma unroll
    for (int r = 0; r < 8; r++) {
        int v = v0 + r;
        if (v < VOCAB) {
            float lo, hi;
            unpack2(accP[r], lo, hi);
            g_P[v * UNITS + p] = lo + hi + bp;
            unpack2(accQ[r], lo, hi);
            g_P[v * UNITS + p + 16] = lo + hi + bq;
        }
    }
}

// ---------------------------------------------------------------------------
// Kernel 2: RNN recurrence + head. ROUND-10 VERSION VERBATIM (63.2us,
// reproduced three times — the single-warp chain is the floor for this
// formulation; layout 128 blocks x 4 warps is optimal for 512 rows).
// ---------------------------------------------------------------------------
#define R_WARPS   4
#define R_THREADS 128
#define TOKPAD    (MAXLEN + 8)

__global__ void __launch_bounds__(R_THREADS, 1)
rnn_kernel(const int*   __restrict__ tokens,
           const float* __restrict__ W1,
           const float* __restrict__ b1,
           const float* __restrict__ W2,
           const float* __restrict__ b2,
           const float* __restrict__ Wh,
           float*       __restrict__ out)
{
    __shared__ __align__(16) float h_s[R_WARPS][2][UNITS];
    __shared__ __align__(16) int tok_s[R_WARPS][TOKPAD];

    const unsigned FULL = 0xffffffffu;
    const int tid  = threadIdx.x;
    const int lane = tid & 31;
    const int wid  = tid >> 5;
    const int b    = blockIdx.x * R_WARPS + wid;

    // stage this block's 4 token rows (int4), pad 8 entries per row with 0
    {
        const int4* src = reinterpret_cast<const int4*>(tokens + blockIdx.x * R_WARPS * MAXLEN);
        #pragma unroll
        for (int i = tid; i < R_WARPS * (MAXLEN / 4); i += R_THREADS) {
            int row = i >> 7;
            int col = i & 127;
            reinterpret_cast<int4*>(&tok_s[row][0])[col] = src[i];
        }
        if (tid < R_WARPS * 8)
            tok_s[tid >> 3][MAXLEN + (tid & 7)] = 0;
    }
    __syncthreads();

    // packed weights: whp[p] = {Wh[2p][lane], Wh[2p+1][lane]}
    ull whp[UNITS / 2];
    #pragma unroll
    for (int p = 0; p < UNITS / 2; p++)
        whp[p] = pack2(Wh[(2 * p) * UNITS + lane], Wh[(2 * p + 1) * UNITS + lane]);

    const int* trow = tok_s[wid];

    // prefetch ring: P rows for steps t, t+1, t+2 plus the TOKEN for t+3
    float pv0 = g_P[trow[0] * UNITS + lane];
    float pv1 = g_P[trow[1] * UNITS + lane];
    float pv2 = g_P[trow[2] * UNITS + lane];
    int   tokn = trow[3];

    float h = 0.f;

    #pragma unroll 4
    for (int t = 0; t < MAXLEN; t++) {
        // LDG uses a register token (loaded last iteration) -> no LDS stall
        float pv3 = g_P[tokn * UNITS + lane];
        // token for step t+4, consumed NEXT iteration (padded: no bounds SEL)
        int toknext = trow[t + 4];

        // exchange h across the warp (double-buffered, one syncwarp)
        float* buf = h_s[wid][t & 1];
        buf[lane] = h;
        __syncwarp();
        const ulonglong2* hb = reinterpret_cast<const ulonglong2*>(buf);
        ulonglong2 v0 = hb[0], v1 = hb[1], v2 = hb[2], v3 = hb[3];
        ulonglong2 v4 = hb[4], v5 = hb[5], v6 = hb[6], v7 = hb[7];

        // 8 chains of depth 2
        ull A0 = fma2(v0.x, whp[0],  pack2(pv0, 0.f));
        ull A1 = fma2(v0.y, whp[1],  0ULL);
        ull A2 = fma2(v1.x, whp[2],  0ULL);
        ull A3 = fma2(v1.y, whp[3],  0ULL);
        ull A4 = fma2(v2.x, whp[4],  0ULL);
        ull A5 = fma2(v2.y, whp[5],  0ULL);
        ull A6 = fma2(v3.x, whp[6],  0ULL);
        ull A7 = fma2(v3.y, whp[7],  0ULL);
        A0 = fma2(v4.x, whp[8],  A0);
        A1 = fma2(v4.y, whp[9],  A1);
        A2 = fma2(v5.x, whp[10], A2);
        A3 = fma2(v5.y, whp[11], A3);
        A4 = fma2(v6.x, whp[12], A4);
        A5 = fma2(v6.y, whp[13], A5);
        A6 = fma2(v7.x, whp[14], A6);
        A7 = fma2(v7.y, whp[15], A7);

        ull B0 = add2(A0, A1), B1 = add2(A2, A3);
        ull B2 = add2(A4, A5), B3 = add2(A6, A7);
        ull D  = add2(add2(B0, B1), add2(B2, B3));
        float zlo, zhi; unpack2(D, zlo, zhi);

        h = tanhf_mufu(zlo + zhi);

        pv0 = pv1; pv1 = pv2; pv2 = pv3; tokn = toknext;
    }

    // ---- head: z = (h @ W1 + b1) @ W2 + b2 ; out = sigmoid(z) ----
    float w1c[UNITS];
    #pragma unroll
    for (int k = 0; k < UNITS; k++)
        w1c[k] = (lane < F1) ? W1[k * F1 + lane] : 0.f;

    float y = (lane < F1) ? b1[lane] : 0.f;
    #pragma unroll
    for (int k = 0; k < UNITS; k++)
        y = fmaf(__shfl_sync(FULL, h, k), w1c[k], y);

    float w2v = (lane < F1) ? W2[lane] : 0.f;
    float contrib = y * w2v;
    #pragma unroll
    for (int off = 16; off > 0; off >>= 1)
        contrib += __shfl_xor_sync(FULL, contrib, off);

    if (lane == 0) {
        float zz = contrib + b2[0];
        out[b] = rcpf(1.f + ex2f(-1.4426950408889634f * zz));
    }
}

// ---------------------------------------------------------------------------
extern "C" void kernel_launch(void* const* d_in, const int* in_sizes, int n_in,
                              void* d_out, int out_size)
{
    const int*   tokens = (const int*)  d_in[0];
    const float* emb    = (const float*)d_in[1];
    const float* Wx     = (const float*)d_in[2];
    const float* Wh     = (const float*)d_in[3];
    const float* bias   = (const float*)d_in[4];
    const float* W1     = (const float*)d_in[5];
    const float* b1     = (const float*)d_in[6];
    const float* W2     = (const float*)d_in[7];
    const float* b2     = (const float*)d_in[8];
    float* out = (float*)d_out;

    cudaFuncSetAttribute((const void*)compute_P_kernel,
                         cudaFuncAttributeMaxDynamicSharedMemorySize, PK_SMEM);

    compute_P_kernel<<<(VOCAB + PK_BLOCK_ROWS - 1) / PK_BLOCK_ROWS, PK_THREADS, PK_SMEM>>>(emb, Wx, bias);
    rnn_kernel<<<BATCH / R_WARPS, R_THREADS>>>(tokens, W1, b1, W2, b2, Wh, out);
}

// round 15
// speedup vs baseline: 1.2866x; 1.1266x over previous
#include <cuda_runtime.h>

#define VOCAB  50000
#define EMBED  256
#define MAXLEN 512
#define UNITS  32
#define F1     16
#define BATCH  512

typedef unsigned long long ull;

// Scratch: P = emb_table @ Wx + b  [VOCAB, UNITS]  (6.4 MB, L2-resident)
__device__ float g_P[VOCAB * UNITS];

// ---- packed / MUFU / async helpers (sm_103a) -------------------------------
__device__ __forceinline__ ull pack2(float lo, float hi) {
    ull d; asm("mov.b64 %0, {%1, %2};" : "=l"(d) : "f"(lo), "f"(hi)); return d;
}
__device__ __forceinline__ ull fma2(ull a, ull b, ull c) {
    ull d; asm("fma.rn.f32x2 %0, %1, %2, %3;" : "=l"(d) : "l"(a), "l"(b), "l"(c)); return d;
}
__device__ __forceinline__ ull add2(ull a, ull b) {
    ull d; asm("add.rn.f32x2 %0, %1, %2;" : "=l"(d) : "l"(a), "l"(b)); return d;
}
__device__ __forceinline__ void unpack2(ull s, float& lo, float& hi) {
    asm("mov.b64 {%0, %1}, %2;" : "=f"(lo), "=f"(hi) : "l"(s));
}
__device__ __forceinline__ float ex2f(float x) {
    float y; asm("ex2.approx.f32 %0, %1;" : "=f"(y) : "f"(x)); return y;
}
__device__ __forceinline__ float rcpf(float x) {
    float y; asm("rcp.approx.f32 %0, %1;" : "=f"(y) : "f"(x)); return y;
}
__device__ __forceinline__ float tanhf_mufu(float x) {
    float y; asm("tanh.approx.f32 %0, %1;" : "=f"(y) : "f"(x)); return y;
}
__device__ __forceinline__ unsigned smem_u32(const void* p) {
    return (unsigned)__cvta_generic_to_shared(p);
}
#define CP_ASYNC16(dst_u32, src_ptr) \
    asm volatile("cp.async.ca.shared.global [%0], [%1], 16;" :: "r"(dst_u32), "l"(src_ptr))
#define CP_COMMIT()  asm volatile("cp.async.commit_group;")
#define CP_WAIT1()   asm volatile("cp.async.wait_group 1;")

// ---------------------------------------------------------------------------
// Kernel 1: P[v][j] = sum_e emb[v][e]*Wx[e][j] + b[j]
// Round-9 math (64-row tile, 2 cols x 8 rows/thread, stride-258 wxT,
// LDS.64 weights) with the emb tile split into 4 e-chunks of 64 cols
// (16KB), DOUBLE-BUFFERED via cp.async: per-chunk DRAM (~570cyc) hides
// under per-chunk compute (~1024 fma2-cyc), removing the ~2300cyc of
// serially-exposed staging that kept round 9 at 16.7us vs ~11.4 roofline.
// smem 97KB -> 65KB also gives 3 blocks/SM for cross-block overlap.
// ---------------------------------------------------------------------------
#define PK_ROWS      64
#define PK_THREADS   128
#define WXT_STRIDE   258
#define PK_CH        64                          // e-chunk width (floats)
#define PK_NCH       (EMBED / PK_CH)             // 4 chunks
#define CHUNK_FLOATS (PK_ROWS * PK_CH)           // 4096 floats = 16KB
#define PK_SMEM      ((UNITS * WXT_STRIDE + 2 * CHUNK_FLOATS) * 4)  // ~65KB

__global__ void __launch_bounds__(PK_THREADS)
compute_P_kernel(const float* __restrict__ emb, const float* __restrict__ Wx,
                 const float* __restrict__ bias)
{
    extern __shared__ float smem[];
    float* wxT = smem;                                    // [UNITS][WXT_STRIDE]
    float* ebuf0 = smem + UNITS * WXT_STRIDE;             // chunk buffers
    float* ebuf1 = ebuf0 + CHUNK_FLOATS;

    const int tid = threadIdx.x;
    const int v0  = blockIdx.x * PK_ROWS;

    // stage one 16KB e-chunk (rows clamped: OOB rows read row VOCAB-1)
    auto stage = [&](int c, float* dst) {
        const int e0 = c * PK_CH;
        #pragma unroll
        for (int k = 0; k < 8; k++) {
            int seg  = tid + k * PK_THREADS;     // 0..1023 (64 rows x 16 seg)
            int row  = seg >> 4;
            int col4 = (seg & 15) << 2;
            int vg = v0 + row; if (vg >= VOCAB) vg = VOCAB - 1;
            const float* src = emb + (size_t)vg * EMBED + e0 + col4;
            CP_ASYNC16(smem_u32(dst + row * PK_CH + col4), src);
        }
    };

    // kick off chunks 0 and 1 immediately (DRAM starts flowing)
    stage(0, ebuf0); CP_COMMIT();
    stage(1, ebuf1); CP_COMMIT();

    // stage Wx transposed while the cp.asyncs fly
    #pragma unroll
    for (int i = tid; i < EMBED * UNITS; i += PK_THREADS) {
        int j = i & 31, e = i >> 5;
        wxT[j * WXT_STRIDE + e] = Wx[i];
    }

    const int p  = tid & 15;          // columns p and p+16
    const int rg = tid >> 4;          // rows rg*8 .. rg*8+7

    const ull* wp = reinterpret_cast<const ull*>(wxT + p * WXT_STRIDE);
    const ull* wq = reinterpret_cast<const ull*>(wxT + (p + 16) * WXT_STRIDE);

    ull accP[8] = {0,0,0,0,0,0,0,0}, accQ[8] = {0,0,0,0,0,0,0,0};

    #pragma unroll
    for (int c = 0; c < PK_NCH; c++) {
        float* buf = (c & 1) ? ebuf1 : ebuf0;
        CP_WAIT1();                   // chunk c landed (c+1 may be in flight)
        __syncthreads();              // visibility + wxT ready on c==0

        const float* er = buf + rg * 8 * PK_CH;
        const int ew0 = c * PK_CH;    // global e offset for weights

        #pragma unroll
        for (int e = 0; e < PK_CH; e += 4) {
            ull wp0 = wp[(ew0 + e) >> 1];
            ull wp1 = wp[((ew0 + e) >> 1) + 1];
            ull wq0 = wq[(ew0 + e) >> 1];
            ull wq1 = wq[((ew0 + e) >> 1) + 1];
            #pragma unroll
            for (int r = 0; r < 8; r++) {
                ulonglong2 ev = *reinterpret_cast<const ulonglong2*>(er + r * PK_CH + e);
                accP[r] = fma2(ev.x, wp0, accP[r]);
                accP[r] = fma2(ev.y, wp1, accP[r]);
                accQ[r] = fma2(ev.x, wq0, accQ[r]);
                accQ[r] = fma2(ev.y, wq1, accQ[r]);
            }
        }

        __syncthreads();              // all threads done with buf
        if (c + 2 < PK_NCH) { stage(c + 2, buf); }
        CP_COMMIT();                  // (possibly empty) group keeps counts aligned
    }

    const float bp = bias[p], bq = bias[p + 16];
    #pragma unroll
    for (int r = 0; r < 8; r++) {
        int v = v0 + rg * 8 + r;
        if (v < VOCAB) {
            float lo, hi;
            unpack2(accP[r], lo, hi);
            g_P[v * UNITS + p] = lo + hi + bp;
            unpack2(accQ[r], lo, hi);
            g_P[v * UNITS + p + 16] = lo + hi + bq;
        }
    }
}

// ---------------------------------------------------------------------------
// Kernel 2: RNN recurrence + head. ROUND-10 VERSION VERBATIM (62.5-63.2us,
// reproduced four times — single-warp chain floor for this formulation).
// ---------------------------------------------------------------------------
#define R_WARPS   4
#define R_THREADS 128
#define TOKPAD    (MAXLEN + 8)

__global__ void __launch_bounds__(R_THREADS, 1)
rnn_kernel(const int*   __restrict__ tokens,
           const float* __restrict__ W1,
           const float* __restrict__ b1,
           const float* __restrict__ W2,
           const float* __restrict__ b2,
           const float* __restrict__ Wh,
           float*       __restrict__ out)
{
    __shared__ __align__(16) float h_s[R_WARPS][2][UNITS];
    __shared__ __align__(16) int tok_s[R_WARPS][TOKPAD];

    const unsigned FULL = 0xffffffffu;
    const int tid  = threadIdx.x;
    const int lane = tid & 31;
    const int wid  = tid >> 5;
    const int b    = blockIdx.x * R_WARPS + wid;

    // stage this block's 4 token rows (int4), pad 8 entries per row with 0
    {
        const int4* src = reinterpret_cast<const int4*>(tokens + blockIdx.x * R_WARPS * MAXLEN);
        #pragma unroll
        for (int i = tid; i < R_WARPS * (MAXLEN / 4); i += R_THREADS) {
            int row = i >> 7;
            int col = i & 127;
            reinterpret_cast<int4*>(&tok_s[row][0])[col] = src[i];
        }
        if (tid < R_WARPS * 8)
            tok_s[tid >> 3][MAXLEN + (tid & 7)] = 0;
    }
    __syncthreads();

    // packed weights: whp[p] = {Wh[2p][lane], Wh[2p+1][lane]}
    ull whp[UNITS / 2];
    #pragma unroll
    for (int p = 0; p < UNITS / 2; p++)
        whp[p] = pack2(Wh[(2 * p) * UNITS + lane], Wh[(2 * p + 1) * UNITS + lane]);

    const int* trow = tok_s[wid];

    // prefetch ring: P rows for steps t, t+1, t+2 plus the TOKEN for t+3
    float pv0 = g_P[trow[0] * UNITS + lane];
    float pv1 = g_P[trow[1] * UNITS + lane];
    float pv2 = g_P[trow[2] * UNITS + lane];
    int   tokn = trow[3];

    float h = 0.f;

    #pragma unroll 4
    for (int t = 0; t < MAXLEN; t++) {
        // LDG uses a register token (loaded last iteration) -> no LDS stall
        float pv3 = g_P[tokn * UNITS + lane];
        // token for step t+4, consumed NEXT iteration (padded: no bounds SEL)
        int toknext = trow[t + 4];

        // exchange h across the warp (double-buffered, one syncwarp)
        float* buf = h_s[wid][t & 1];
        buf[lane] = h;
        __syncwarp();
        const ulonglong2* hb = reinterpret_cast<const ulonglong2*>(buf);
        ulonglong2 v0 = hb[0], v1 = hb[1], v2 = hb[2], v3 = hb[3];
        ulonglong2 v4 = hb[4], v5 = hb[5], v6 = hb[6], v7 = hb[7];

        // 8 chains of depth 2
        ull A0 = fma2(v0.x, whp[0],  pack2(pv0, 0.f));
        ull A1 = fma2(v0.y, whp[1],  0ULL);
        ull A2 = fma2(v1.x, whp[2],  0ULL);
        ull A3 = fma2(v1.y, whp[3],  0ULL);
        ull A4 = fma2(v2.x, whp[4],  0ULL);
        ull A5 = fma2(v2.y, whp[5],  0ULL);
        ull A6 = fma2(v3.x, whp[6],  0ULL);
        ull A7 = fma2(v3.y, whp[7],  0ULL);
        A0 = fma2(v4.x, whp[8],  A0);
        A1 = fma2(v4.y, whp[9],  A1);
        A2 = fma2(v5.x, whp[10], A2);
        A3 = fma2(v5.y, whp[11], A3);
        A4 = fma2(v6.x, whp[12], A4);
        A5 = fma2(v6.y, whp[13], A5);
        A6 = fma2(v7.x, whp[14], A6);
        A7 = fma2(v7.y, whp[15], A7);

        ull B0 = add2(A0, A1), B1 = add2(A2, A3);
        ull B2 = add2(A4, A5), B3 = add2(A6, A7);
        ull D  = add2(add2(B0, B1), add2(B2, B3));
        float zlo, zhi; unpack2(D, zlo, zhi);

        h = tanhf_mufu(zlo + zhi);

        pv0 = pv1; pv1 = pv2; pv2 = pv3; tokn = toknext;
    }

    // ---- head: z = (h @ W1 + b1) @ W2 + b2 ; out = sigmoid(z) ----
    float w1c[UNITS];
    #pragma unroll
    for (int k = 0; k < UNITS; k++)
        w1c[k] = (lane < F1) ? W1[k * F1 + lane] : 0.f;

    float y = (lane < F1) ? b1[lane] : 0.f;
    #pragma unroll
    for (int k = 0; k < UNITS; k++)
        y = fmaf(__shfl_sync(FULL, h, k), w1c[k], y);

    float w2v = (lane < F1) ? W2[lane] : 0.f;
    float contrib = y * w2v;
    #pragma unroll
    for (int off = 16; off > 0; off >>= 1)
        contrib += __shfl_xor_sync(FULL, contrib, off);

    if (lane == 0) {
        float zz = contrib + b2[0];
        out[b] = rcpf(1.f + ex2f(-1.4426950408889634f * zz));
    }
}

// ---------------------------------------------------------------------------
extern "C" void kernel_launch(void* const* d_in, const int* in_sizes, int n_in,
                              void* d_out, int out_size)
{
    const int*   tokens = (const int*)  d_in[0];
    const float* emb    = (const float*)d_in[1];
    const float* Wx     = (const float*)d_in[2];
    const float* Wh     = (const float*)d_in[3];
    const float* bias   = (const float*)d_in[4];
    const float* W1     = (const float*)d_in[5];
    const float* b1     = (const float*)d_in[6];
    const float* W2     = (const float*)d_in[7];
    const float* b2     = (const float*)d_in[8];
    float* out = (float*)d_out;

    cudaFuncSetAttribute((const void*)compute_P_kernel,
                         cudaFuncAttributeMaxDynamicSharedMemorySize, PK_SMEM);

    compute_P_kernel<<<(VOCAB + PK_ROWS - 1) / PK_ROWS, PK_THREADS, PK_SMEM>>>(emb, Wx, bias);
    rnn_kernel<<<BATCH / R_WARPS, R_THREADS>>>(tokens, W1, b1, W2, b2, Wh, out);
}

// round 16
// speedup vs baseline: 1.2893x; 1.0020x over previous
#include <cuda_runtime.h>

#define VOCAB  50000
#define EMBED  256
#define MAXLEN 512
#define UNITS  32
#define F1     16
#define BATCH  512

typedef unsigned long long ull;

// Scratch: P = emb_table @ Wx + b  [VOCAB, UNITS]  (6.4 MB, L2-resident)
__device__ float g_P[VOCAB * UNITS];

// ---- packed / MUFU / async helpers (sm_103a) -------------------------------
__device__ __forceinline__ ull pack2(float lo, float hi) {
    ull d; asm("mov.b64 %0, {%1, %2};" : "=l"(d) : "f"(lo), "f"(hi)); return d;
}
__device__ __forceinline__ ull fma2(ull a, ull b, ull c) {
    ull d; asm("fma.rn.f32x2 %0, %1, %2, %3;" : "=l"(d) : "l"(a), "l"(b), "l"(c)); return d;
}
__device__ __forceinline__ ull add2(ull a, ull b) {
    ull d; asm("add.rn.f32x2 %0, %1, %2;" : "=l"(d) : "l"(a), "l"(b)); return d;
}
__device__ __forceinline__ void unpack2(ull s, float& lo, float& hi) {
    asm("mov.b64 {%0, %1}, %2;" : "=f"(lo), "=f"(hi) : "l"(s));
}
__device__ __forceinline__ float ex2f(float x) {
    float y; asm("ex2.approx.f32 %0, %1;" : "=f"(y) : "f"(x)); return y;
}
__device__ __forceinline__ float rcpf(float x) {
    float y; asm("rcp.approx.f32 %0, %1;" : "=f"(y) : "f"(x)); return y;
}
__device__ __forceinline__ float tanhf_mufu(float x) {
    float y; asm("tanh.approx.f32 %0, %1;" : "=f"(y) : "f"(x)); return y;
}
__device__ __forceinline__ unsigned smem_u32(const void* p) {
    return (unsigned)__cvta_generic_to_shared(p);
}
#define CP_ASYNC16(dst_u32, src_ptr) \
    asm volatile("cp.async.ca.shared.global [%0], [%1], 16;" :: "r"(dst_u32), "l"(src_ptr))
#define CP_COMMIT()  asm volatile("cp.async.commit_group;")
#define CP_WAIT2()   asm volatile("cp.async.wait_group 2;")

// ---------------------------------------------------------------------------
// Kernel 1: P[v][j] = sum_e emb[v][e]*Wx[e][j] + b[j]
// Round-15 structure with FINER pipeline: 8 e-chunks of 32 cols (8KB),
// 3-buffer ring, 2 chunks always in flight (wait_group 2). Halves the
// cold-start/tail bubble that kept round 15 at 14.0us vs 11.4 roofline.
// smem 57KB -> 3 blocks/SM (pinned via launch_bounds) for cross-block
// overlap. Math per thread unchanged: 2 cols (p, p+16) x 8 rows, packed
// K-pair partials, stride-258 wxT, LDS.64 weight loads.
// ---------------------------------------------------------------------------
#define PK_ROWS      64
#define PK_THREADS   128
#define WXT_STRIDE   258
#define PK_CH        32                          // e-chunk width (floats)
#define PK_NCH       (EMBED / PK_CH)             // 8 chunks
#define PK_NBUF      3
#define CHUNK_FLOATS (PK_ROWS * PK_CH)           // 2048 floats = 8KB
#define PK_SMEM      ((UNITS * WXT_STRIDE + PK_NBUF * CHUNK_FLOATS) * 4)  // ~57KB

__global__ void __launch_bounds__(PK_THREADS, 3)
compute_P_kernel(const float* __restrict__ emb, const float* __restrict__ Wx,
                 const float* __restrict__ bias)
{
    extern __shared__ float smem[];
    float* wxT  = smem;                                   // [UNITS][WXT_STRIDE]
    float* ring = smem + UNITS * WXT_STRIDE;              // 3 x 8KB chunk bufs

    const int tid = threadIdx.x;
    const int v0  = blockIdx.x * PK_ROWS;

    // stage one 8KB e-chunk (rows clamped: OOB rows read row VOCAB-1)
    auto stage = [&](int c, float* dst) {
        const int e0 = c * PK_CH;
        #pragma unroll
        for (int k = 0; k < 4; k++) {
            int seg  = tid + k * PK_THREADS;     // 0..511 (64 rows x 8 seg)
            int row  = seg >> 3;                 // 8 x 16B segments per row
            int col4 = (seg & 7) << 2;
            int vg = v0 + row; if (vg >= VOCAB) vg = VOCAB - 1;
            const float* src = emb + (size_t)vg * EMBED + e0 + col4;
            CP_ASYNC16(smem_u32(dst + row * PK_CH + col4), src);
        }
    };

    // prefetch chunks 0..2 immediately (DRAM starts flowing)
    stage(0, ring + 0 * CHUNK_FLOATS); CP_COMMIT();
    stage(1, ring + 1 * CHUNK_FLOATS); CP_COMMIT();
    stage(2, ring + 2 * CHUNK_FLOATS); CP_COMMIT();

    // stage Wx transposed while the cp.asyncs fly
    #pragma unroll
    for (int i = tid; i < EMBED * UNITS; i += PK_THREADS) {
        int j = i & 31, e = i >> 5;
        wxT[j * WXT_STRIDE + e] = Wx[i];
    }

    const int p  = tid & 15;          // columns p and p+16
    const int rg = tid >> 4;          // rows rg*8 .. rg*8+7

    const ull* wp = reinterpret_cast<const ull*>(wxT + p * WXT_STRIDE);
    const ull* wq = reinterpret_cast<const ull*>(wxT + (p + 16) * WXT_STRIDE);

    ull accP[8] = {0,0,0,0,0,0,0,0}, accQ[8] = {0,0,0,0,0,0,0,0};

    int bufidx = 0;
    #pragma unroll
    for (int c = 0; c < PK_NCH; c++) {
        float* buf = ring + bufidx * CHUNK_FLOATS;
        CP_WAIT2();                   // chunk c landed (c+1, c+2 may fly)
        __syncthreads();              // visibility + wxT ready on c==0

        const float* er = buf + rg * 8 * PK_CH;
        const int ew0 = c * PK_CH;    // global e offset for weights

        #pragma unroll
        for (int e = 0; e < PK_CH; e += 4) {
            ull wp0 = wp[(ew0 + e) >> 1];
            ull wp1 = wp[((ew0 + e) >> 1) + 1];
            ull wq0 = wq[(ew0 + e) >> 1];
            ull wq1 = wq[((ew0 + e) >> 1) + 1];
            #pragma unroll
            for (int r = 0; r < 8; r++) {
                ulonglong2 ev = *reinterpret_cast<const ulonglong2*>(er + r * PK_CH + e);
                accP[r] = fma2(ev.x, wp0, accP[r]);
                accP[r] = fma2(ev.y, wp1, accP[r]);
                accQ[r] = fma2(ev.x, wq0, accQ[r]);
                accQ[r] = fma2(ev.y, wq1, accQ[r]);
            }
        }

        __syncthreads();              // all threads done with buf
        if (c + PK_NBUF < PK_NCH) { stage(c + PK_NBUF, buf); }
        CP_COMMIT();                  // one group per iter keeps counts aligned

        bufidx = (bufidx + 1 == PK_NBUF) ? 0 : bufidx + 1;
    }

    const float bp = bias[p], bq = bias[p + 16];
    #pragma unroll
    for (int r = 0; r < 8; r++) {
        int v = v0 + rg * 8 + r;
        if (v < VOCAB) {
            float lo, hi;
            unpack2(accP[r], lo, hi);
            g_P[v * UNITS + p] = lo + hi + bp;
            unpack2(accQ[r], lo, hi);
            g_P[v * UNITS + p + 16] = lo + hi + bq;
        }
    }
}

// ---------------------------------------------------------------------------
// Kernel 2: RNN recurrence + head. ROUND-10 VERSION VERBATIM (62.5-63.6us,
// reproduced five times — single-warp chain floor for this formulation).
// ---------------------------------------------------------------------------
#define R_WARPS   4
#define R_THREADS 128
#define TOKPAD    (MAXLEN + 8)

__global__ void __launch_bounds__(R_THREADS, 1)
rnn_kernel(const int*   __restrict__ tokens,
           const float* __restrict__ W1,
           const float* __restrict__ b1,
           const float* __restrict__ W2,
           const float* __restrict__ b2,
           const float* __restrict__ Wh,
           float*       __restrict__ out)
{
    __shared__ __align__(16) float h_s[R_WARPS][2][UNITS];
    __shared__ __align__(16) int tok_s[R_WARPS][TOKPAD];

    const unsigned FULL = 0xffffffffu;
    const int tid  = threadIdx.x;
    const int lane = tid & 31;
    const int wid  = tid >> 5;
    const int b    = blockIdx.x * R_WARPS + wid;

    // stage this block's 4 token rows (int4), pad 8 entries per row with 0
    {
        const int4* src = reinterpret_cast<const int4*>(tokens + blockIdx.x * R_WARPS * MAXLEN);
        #pragma unroll
        for (int i = tid; i < R_WARPS * (MAXLEN / 4); i += R_THREADS) {
            int row = i >> 7;
            int col = i & 127;
            reinterpret_cast<int4*>(&tok_s[row][0])[col] = src[i];
        }
        if (tid < R_WARPS * 8)
            tok_s[tid >> 3][MAXLEN + (tid & 7)] = 0;
    }
    __syncthreads();

    // packed weights: whp[p] = {Wh[2p][lane], Wh[2p+1][lane]}
    ull whp[UNITS / 2];
    #pragma unroll
    for (int p = 0; p < UNITS / 2; p++)
        whp[p] = pack2(Wh[(2 * p) * UNITS + lane], Wh[(2 * p + 1) * UNITS + lane]);

    const int* trow = tok_s[wid];

    // prefetch ring: P rows for steps t, t+1, t+2 plus the TOKEN for t+3
    float pv0 = g_P[trow[0] * UNITS + lane];
    float pv1 = g_P[trow[1] * UNITS + lane];
    float pv2 = g_P[trow[2] * UNITS + lane];
    int   tokn = trow[3];

    float h = 0.f;

    #pragma unroll 4
    for (int t = 0; t < MAXLEN; t++) {
        // LDG uses a register token (loaded last iteration) -> no LDS stall
        float pv3 = g_P[tokn * UNITS + lane];
        // token for step t+4, consumed NEXT iteration (padded: no bounds SEL)
        int toknext = trow[t + 4];

        // exchange h across the warp (double-buffered, one syncwarp)
        float* buf = h_s[wid][t & 1];
        buf[lane] = h;
        __syncwarp();
        const ulonglong2* hb = reinterpret_cast<const ulonglong2*>(buf);
        ulonglong2 v0 = hb[0], v1 = hb[1], v2 = hb[2], v3 = hb[3];
        ulonglong2 v4 = hb[4], v5 = hb[5], v6 = hb[6], v7 = hb[7];

        // 8 chains of depth 2
        ull A0 = fma2(v0.x, whp[0],  pack2(pv0, 0.f));
        ull A1 = fma2(v0.y, whp[1],  0ULL);
        ull A2 = fma2(v1.x, whp[2],  0ULL);
        ull A3 = fma2(v1.y, whp[3],  0ULL);
        ull A4 = fma2(v2.x, whp[4],  0ULL);
        ull A5 = fma2(v2.y, whp[5],  0ULL);
        ull A6 = fma2(v3.x, whp[6],  0ULL);
        ull A7 = fma2(v3.y, whp[7],  0ULL);
        A0 = fma2(v4.x, whp[8],  A0);
        A1 = fma2(v4.y, whp[9],  A1);
        A2 = fma2(v5.x, whp[10], A2);
        A3 = fma2(v5.y, whp[11], A3);
        A4 = fma2(v6.x, whp[12], A4);
        A5 = fma2(v6.y, whp[13], A5);
        A6 = fma2(v7.x, whp[14], A6);
        A7 = fma2(v7.y, whp[15], A7);

        ull B0 = add2(A0, A1), B1 = add2(A2, A3);
        ull B2 = add2(A4, A5), B3 = add2(A6, A7);
        ull D  = add2(add2(B0, B1), add2(B2, B3));
        float zlo, zhi; unpack2(D, zlo, zhi);

        h = tanhf_mufu(zlo + zhi);

        pv0 = pv1; pv1 = pv2; pv2 = pv3; tokn = toknext;
    }

    // ---- head: z = (h @ W1 + b1) @ W2 + b2 ; out = sigmoid(z) ----
    float w1c[UNITS];
    #pragma unroll
    for (int k = 0; k < UNITS; k++)
        w1c[k] = (lane < F1) ? W1[k * F1 + lane] : 0.f;

    float y = (lane < F1) ? b1[lane] : 0.f;
    #pragma unroll
    for (int k = 0; k < UNITS; k++)
        y = fmaf(__shfl_sync(FULL, h, k), w1c[k], y);

    float w2v = (lane < F1) ? W2[lane] : 0.f;
    float contrib = y * w2v;
    #pragma unroll
    for (int off = 16; off > 0; off >>= 1)
        contrib += __shfl_xor_sync(FULL, contrib, off);

    if (lane == 0) {
        float zz = contrib + b2[0];
        out[b] = rcpf(1.f + ex2f(-1.4426950408889634f * zz));
    }
}

// ---------------------------------------------------------------------------
extern "C" void kernel_launch(void* const* d_in, const int* in_sizes, int n_in,
                              void* d_out, int out_size)
{
    const int*   tokens = (const int*)  d_in[0];
    const float* emb    = (const float*)d_in[1];
    const float* Wx     = (const float*)d_in[2];
    const float* Wh     = (const float*)d_in[3];
    const float* bias   = (const float*)d_in[4];
    const float* W1     = (const float*)d_in[5];
    const float* b1     = (const float*)d_in[6];
    const float* W2     = (const float*)d_in[7];
    const float* b2     = (const float*)d_in[8];
    float* out = (float*)d_out;

    cudaFuncSetAttribute((const void*)compute_P_kernel,
                         cudaFuncAttributeMaxDynamicSharedMemorySize, PK_SMEM);

    compute_P_kernel<<<(VOCAB + PK_ROWS - 1) / PK_ROWS, PK_THREADS, PK_SMEM>>>(emb, Wx, bias);
    rnn_kernel<<<BATCH / R_WARPS, R_THREADS>>>(tokens, W1, b1, W2, b2, Wh, out);
}

// round 17
// speedup vs baseline: 1.3350x; 1.0355x over previous
#include <cuda_runtime.h>

#define VOCAB  50000
#define EMBED  256
#define MAXLEN 512
#define UNITS  32
#define F1     16
#define BATCH  512

typedef unsigned long long ull;

// Scratch: P = emb_table @ Wx + b  [VOCAB, UNITS]  (6.4 MB, L2-resident)
__device__ float g_P[VOCAB * UNITS];

// ---- packed / MUFU / async helpers (sm_103a) -------------------------------
__device__ __forceinline__ ull pack2(float lo, float hi) {
    ull d; asm("mov.b64 %0, {%1, %2};" : "=l"(d) : "f"(lo), "f"(hi)); return d;
}
__device__ __forceinline__ ull fma2(ull a, ull b, ull c) {
    ull d; asm("fma.rn.f32x2 %0, %1, %2, %3;" : "=l"(d) : "l"(a), "l"(b), "l"(c)); return d;
}
__device__ __forceinline__ ull add2(ull a, ull b) {
    ull d; asm("add.rn.f32x2 %0, %1, %2;" : "=l"(d) : "l"(a), "l"(b)); return d;
}
__device__ __forceinline__ void unpack2(ull s, float& lo, float& hi) {
    asm("mov.b64 {%0, %1}, %2;" : "=f"(lo), "=f"(hi) : "l"(s));
}
__device__ __forceinline__ float ex2f(float x) {
    float y; asm("ex2.approx.f32 %0, %1;" : "=f"(y) : "f"(x)); return y;
}
__device__ __forceinline__ float rcpf(float x) {
    float y; asm("rcp.approx.f32 %0, %1;" : "=f"(y) : "f"(x)); return y;
}
__device__ __forceinline__ float tanhf_mufu(float x) {
    float y; asm("tanh.approx.f32 %0, %1;" : "=f"(y) : "f"(x)); return y;
}
__device__ __forceinline__ unsigned smem_u32(const void* p) {
    return (unsigned)__cvta_generic_to_shared(p);
}
#define CP_ASYNC16(dst_u32, src_ptr) \
    asm volatile("cp.async.ca.shared.global [%0], [%1], 16;" :: "r"(dst_u32), "l"(src_ptr))
#define CP_COMMIT()  asm volatile("cp.async.commit_group;")
#define CP_WAIT2()   asm volatile("cp.async.wait_group 2;")

// ---------------------------------------------------------------------------
// Kernel 1: P[v][j] = sum_e emb[v][e]*Wx[e][j] + b[j]
// ROUND-16 VERSION VERBATIM (~14us): 8 e-chunks of 32 cols, 3-buffer
// cp.async ring (2 in flight), 57KB smem -> 3 blocks/SM; per thread
// 2 cols (p, p+16) x 8 rows, packed K-pair partials, stride-258 wxT.
// ---------------------------------------------------------------------------
#define PK_ROWS      64
#define PK_THREADS   128
#define WXT_STRIDE   258
#define PK_CH        32
#define PK_NCH       (EMBED / PK_CH)
#define PK_NBUF      3
#define CHUNK_FLOATS (PK_ROWS * PK_CH)
#define PK_SMEM      ((UNITS * WXT_STRIDE + PK_NBUF * CHUNK_FLOATS) * 4)

__global__ void __launch_bounds__(PK_THREADS, 3)
compute_P_kernel(const float* __restrict__ emb, const float* __restrict__ Wx,
                 const float* __restrict__ bias)
{
    extern __shared__ float smem[];
    float* wxT  = smem;
    float* ring = smem + UNITS * WXT_STRIDE;

    const int tid = threadIdx.x;
    const int v0  = blockIdx.x * PK_ROWS;

    auto stage = [&](int c, float* dst) {
        const int e0 = c * PK_CH;
        #pragma unroll
        for (int k = 0; k < 4; k++) {
            int seg  = tid + k * PK_THREADS;
            int row  = seg >> 3;
            int col4 = (seg & 7) << 2;
            int vg = v0 + row; if (vg >= VOCAB) vg = VOCAB - 1;
            const float* src = emb + (size_t)vg * EMBED + e0 + col4;
            CP_ASYNC16(smem_u32(dst + row * PK_CH + col4), src);
        }
    };

    stage(0, ring + 0 * CHUNK_FLOATS); CP_COMMIT();
    stage(1, ring + 1 * CHUNK_FLOATS); CP_COMMIT();
    stage(2, ring + 2 * CHUNK_FLOATS); CP_COMMIT();

    #pragma unroll
    for (int i = tid; i < EMBED * UNITS; i += PK_THREADS) {
        int j = i & 31, e = i >> 5;
        wxT[j * WXT_STRIDE + e] = Wx[i];
    }

    const int p  = tid & 15;
    const int rg = tid >> 4;

    const ull* wp = reinterpret_cast<const ull*>(wxT + p * WXT_STRIDE);
    const ull* wq = reinterpret_cast<const ull*>(wxT + (p + 16) * WXT_STRIDE);

    ull accP[8] = {0,0,0,0,0,0,0,0}, accQ[8] = {0,0,0,0,0,0,0,0};

    int bufidx = 0;
    #pragma unroll
    for (int c = 0; c < PK_NCH; c++) {
        float* buf = ring + bufidx * CHUNK_FLOATS;
        CP_WAIT2();
        __syncthreads();

        const float* er = buf + rg * 8 * PK_CH;
        const int ew0 = c * PK_CH;

        #pragma unroll
        for (int e = 0; e < PK_CH; e += 4) {
            ull wp0 = wp[(ew0 + e) >> 1];
            ull wp1 = wp[((ew0 + e) >> 1) + 1];
            ull wq0 = wq[(ew0 + e) >> 1];
            ull wq1 = wq[((ew0 + e) >> 1) + 1];
            #pragma unroll
            for (int r = 0; r < 8; r++) {
                ulonglong2 ev = *reinterpret_cast<const ulonglong2*>(er + r * PK_CH + e);
                accP[r] = fma2(ev.x, wp0, accP[r]);
                accP[r] = fma2(ev.y, wp1, accP[r]);
                accQ[r] = fma2(ev.x, wq0, accQ[r]);
                accQ[r] = fma2(ev.y, wq1, accQ[r]);
            }
        }

        __syncthreads();
        if (c + PK_NBUF < PK_NCH) { stage(c + PK_NBUF, buf); }
        CP_COMMIT();

        bufidx = (bufidx + 1 == PK_NBUF) ? 0 : bufidx + 1;
    }

    const float bp = bias[p], bq = bias[p + 16];
    #pragma unroll
    for (int r = 0; r < 8; r++) {
        int v = v0 + rg * 8 + r;
        if (v < VOCAB) {
            float lo, hi;
            unpack2(accP[r], lo, hi);
            g_P[v * UNITS + p] = lo + hi + bp;
            unpack2(accQ[r], lo, hi);
            g_P[v * UNITS + p + 16] = lo + hi + bq;
        }
    }
}

// ---------------------------------------------------------------------------
// Kernel 2: RNN recurrence + head. ROUND-10 BODY VERBATIM, launched with
// PROGRAMMATIC DEPENDENT LAUNCH: the g_P-independent preamble (token
// staging, Wh/W1/W2 loads) runs overlapped with compute_P_kernel's tail;
// cudaGridDependencySynchronize() gates the first g_P read (P kernel sets
// no explicit trigger -> sync waits for full completion + memory flush).
// ---------------------------------------------------------------------------
#define R_WARPS   4
#define R_THREADS 128
#define TOKPAD    (MAXLEN + 8)

__global__ void __launch_bounds__(R_THREADS, 1)
rnn_kernel(const int*   __restrict__ tokens,
           const float* __restrict__ W1,
           const float* __restrict__ b1,
           const float* __restrict__ W2,
           const float* __restrict__ b2,
           const float* __restrict__ Wh,
           float*       __restrict__ out)
{
    __shared__ __align__(16) float h_s[R_WARPS][2][UNITS];
    __shared__ __align__(16) int tok_s[R_WARPS][TOKPAD];

    const unsigned FULL = 0xffffffffu;
    const int tid  = threadIdx.x;
    const int lane = tid & 31;
    const int wid  = tid >> 5;
    const int b    = blockIdx.x * R_WARPS + wid;

    // ---- g_P-independent preamble (overlaps compute_P via PDL) ----
    {
        const int4* src = reinterpret_cast<const int4*>(tokens + blockIdx.x * R_WARPS * MAXLEN);
        #pragma unroll
        for (int i = tid; i < R_WARPS * (MAXLEN / 4); i += R_THREADS) {
            int row = i >> 7;
            int col = i & 127;
            reinterpret_cast<int4*>(&tok_s[row][0])[col] = src[i];
        }
        if (tid < R_WARPS * 8)
            tok_s[tid >> 3][MAXLEN + (tid & 7)] = 0;
    }

    // packed weights: whp[p] = {Wh[2p][lane], Wh[2p+1][lane]}
    ull whp[UNITS / 2];
    #pragma unroll
    for (int p = 0; p < UNITS / 2; p++)
        whp[p] = pack2(Wh[(2 * p) * UNITS + lane], Wh[(2 * p + 1) * UNITS + lane]);

    // head weights (also g_P-independent)
    float w1c[UNITS];
    #pragma unroll
    for (int k = 0; k < UNITS; k++)
        w1c[k] = (lane < F1) ? W1[k * F1 + lane] : 0.f;
    const float b1v = (lane < F1) ? b1[lane] : 0.f;
    const float w2v = (lane < F1) ? W2[lane] : 0.f;
    const float b2v = b2[0];

    __syncthreads();

    // ---- wait for compute_P_kernel's g_P to be complete & visible ----
    cudaGridDependencySynchronize();

    const int* trow = tok_s[wid];

    // prefetch ring: P rows for steps t, t+1, t+2 plus the TOKEN for t+3
    float pv0 = g_P[trow[0] * UNITS + lane];
    float pv1 = g_P[trow[1] * UNITS + lane];
    float pv2 = g_P[trow[2] * UNITS + lane];
    int   tokn = trow[3];

    float h = 0.f;

    #pragma unroll 4
    for (int t = 0; t < MAXLEN; t++) {
        // LDG uses a register token (loaded last iteration) -> no LDS stall
        float pv3 = g_P[tokn * UNITS + lane];
        // token for step t+4, consumed NEXT iteration (padded: no bounds SEL)
        int toknext = trow[t + 4];

        // exchange h across the warp (double-buffered, one syncwarp)
        float* buf = h_s[wid][t & 1];
        buf[lane] = h;
        __syncwarp();
        const ulonglong2* hb = reinterpret_cast<const ulonglong2*>(buf);
        ulonglong2 v0 = hb[0], v1 = hb[1], v2 = hb[2], v3 = hb[3];
        ulonglong2 v4 = hb[4], v5 = hb[5], v6 = hb[6], v7 = hb[7];

        // 8 chains of depth 2
        ull A0 = fma2(v0.x, whp[0],  pack2(pv0, 0.f));
        ull A1 = fma2(v0.y, whp[1],  0ULL);
        ull A2 = fma2(v1.x, whp[2],  0ULL);
        ull A3 = fma2(v1.y, whp[3],  0ULL);
        ull A4 = fma2(v2.x, whp[4],  0ULL);
        ull A5 = fma2(v2.y, whp[5],  0ULL);
        ull A6 = fma2(v3.x, whp[6],  0ULL);
        ull A7 = fma2(v3.y, whp[7],  0ULL);
        A0 = fma2(v4.x, whp[8],  A0);
        A1 = fma2(v4.y, whp[9],  A1);
        A2 = fma2(v5.x, whp[10], A2);
        A3 = fma2(v5.y, whp[11], A3);
        A4 = fma2(v6.x, whp[12], A4);
        A5 = fma2(v6.y, whp[13], A5);
        A6 = fma2(v7.x, whp[14], A6);
        A7 = fma2(v7.y, whp[15], A7);

        ull B0 = add2(A0, A1), B1 = add2(A2, A3);
        ull B2 = add2(A4, A5), B3 = add2(A6, A7);
        ull D  = add2(add2(B0, B1), add2(B2, B3));
        float zlo, zhi; unpack2(D, zlo, zhi);

        h = tanhf_mufu(zlo + zhi);

        pv0 = pv1; pv1 = pv2; pv2 = pv3; tokn = toknext;
    }

    // ---- head: z = (h @ W1 + b1) @ W2 + b2 ; out = sigmoid(z) ----
    float y = b1v;
    #pragma unroll
    for (int k = 0; k < UNITS; k++)
        y = fmaf(__shfl_sync(FULL, h, k), w1c[k], y);

    float contrib = y * w2v;
    #pragma unroll
    for (int off = 16; off > 0; off >>= 1)
        contrib += __shfl_xor_sync(FULL, contrib, off);

    if (lane == 0) {
        float zz = contrib + b2v;
        out[b] = rcpf(1.f + ex2f(-1.4426950408889634f * zz));
    }
}

// ---------------------------------------------------------------------------
extern "C" void kernel_launch(void* const* d_in, const int* in_sizes, int n_in,
                              void* d_out, int out_size)
{
    const int*   tokens = (const int*)  d_in[0];
    const float* emb    = (const float*)d_in[1];
    const float* Wx     = (const float*)d_in[2];
    const float* Wh     = (const float*)d_in[3];
    const float* bias   = (const float*)d_in[4];
    const float* W1     = (const float*)d_in[5];
    const float* b1     = (const float*)d_in[6];
    const float* W2     = (const float*)d_in[7];
    const float* b2     = (const float*)d_in[8];
    float* out = (float*)d_out;

    cudaFuncSetAttribute((const void*)compute_P_kernel,
                         cudaFuncAttributeMaxDynamicSharedMemorySize, PK_SMEM);

    compute_P_kernel<<<(VOCAB + PK_ROWS - 1) / PK_ROWS, PK_THREADS, PK_SMEM>>>(emb, Wx, bias);

    // rnn with programmatic dependent launch: preamble overlaps P's tail
    cudaLaunchConfig_t cfg = {};
    cfg.gridDim  = dim3(BATCH / R_WARPS);
    cfg.blockDim = dim3(R_THREADS);
    cfg.dynamicSmemBytes = 0;
    cfg.stream = 0;
    cudaLaunchAttribute attrs[1];
    attrs[0].id = cudaLaunchAttributeProgrammaticStreamSerialization;
    attrs[0].val.programmaticStreamSerializationAllowed = 1;
    cfg.attrs = attrs;
    cfg.numAttrs = 1;
    cudaLaunchKernelEx(&cfg, rnn_kernel, tokens, W1, b1, W2, b2, Wh, out);
}